// round 17
// baseline (speedup 1.0000x reference)
#include <cuda_runtime.h>
#include <cuda_bf16.h>
#include <cuda_fp16.h>
#include <cstdint>

#define BB   2
#define TT   2048
#define KK   1024
#define HH   16
#define SS   64
#define MROWS (BB*TT)   // 4096
#define INV2048 4.8828125e-4f

// ---- scratch (static device globals; no allocation allowed) ----
__device__ __nv_bfloat16 g_Qh[MROWS*KK], g_Ql[MROWS*KK];
__device__ __nv_bfloat16 g_Kh[MROWS*KK], g_Kl[MROWS*KK];      // compacted K
__device__ __half g_Wuf[KK*KK];
__device__ __half g_Vf [MROWS*KK];                             // compacted V
__device__ __half g_ysf[MROWS*KK];
__device__ int g_idx[BB*TT];
__device__ int g_nv [BB];

// ============================================================================
// helpers
// ============================================================================
__device__ __forceinline__ uint32_t smem_u32(const void* p) {
    uint32_t a;
    asm("{ .reg .u64 t; cvta.to.shared.u64 t, %1; cvt.u32.u64 %0, t; }"
        : "=r"(a) : "l"(p));
    return a;
}

__device__ __forceinline__ void mma_bf16(float d[4],
                                         uint32_t a0, uint32_t a1, uint32_t a2, uint32_t a3,
                                         uint32_t b0, uint32_t b1) {
    asm volatile(
        "mma.sync.aligned.m16n8k16.row.col.f32.bf16.bf16.f32 "
        "{%0,%1,%2,%3}, {%4,%5,%6,%7}, {%8,%9}, {%0,%1,%2,%3};"
        : "+f"(d[0]), "+f"(d[1]), "+f"(d[2]), "+f"(d[3])
        : "r"(a0), "r"(a1), "r"(a2), "r"(a3), "r"(b0), "r"(b1));
}

__device__ __forceinline__ void mma_f16f32(float d[4],
                                           uint32_t a0, uint32_t a1, uint32_t a2, uint32_t a3,
                                           uint32_t b0, uint32_t b1) {
    asm volatile(
        "mma.sync.aligned.m16n8k16.row.col.f32.f16.f16.f32 "
        "{%0,%1,%2,%3}, {%4,%5,%6,%7}, {%8,%9}, {%0,%1,%2,%3};"
        : "+f"(d[0]), "+f"(d[1]), "+f"(d[2]), "+f"(d[3])
        : "r"(a0), "r"(a1), "r"(a2), "r"(a3), "r"(b0), "r"(b1));
}

#define LDSM4(r0, r1, r2, r3, addr) \
    asm volatile("ldmatrix.sync.aligned.m8n8.x4.shared.b16 {%0,%1,%2,%3}, [%4];" \
                 : "=r"(r0), "=r"(r1), "=r"(r2), "=r"(r3) : "r"(addr))

#define LDSM4T(r0, r1, r2, r3, addr) \
    asm volatile("ldmatrix.sync.aligned.m8n8.x4.trans.shared.b16 {%0,%1,%2,%3}, [%4];" \
                 : "=r"(r0), "=r"(r1), "=r"(r2), "=r"(r3) : "r"(addr))

__device__ __forceinline__ void split2(float2 f, uint32_t& h, uint32_t& l) {
    __nv_bfloat162 hh = __float22bfloat162_rn(f);
    float2 hf = __bfloat1622float2(hh);
    __nv_bfloat162 ll = __float22bfloat162_rn(make_float2(f.x - hf.x, f.y - hf.y));
    h = *(uint32_t*)&hh;
    l = *(uint32_t*)&ll;
}

__device__ __forceinline__ void split2h(float2 f, uint32_t& h, uint32_t& l) {
    __half2 hh = __float22half2_rn(f);
    float2 hf = __half22float2(hh);
    __half2 ll = __float22half2_rn(make_float2((f.x - hf.x) * 2048.f,
                                               (f.y - hf.y) * 2048.f));
    h = *(uint32_t*)&hh;
    l = *(uint32_t*)&ll;
}

__device__ __forceinline__ uint32_t pack_h2(float2 f) {
    __half2 hh = __float22half2_rn(f);
    return *(uint32_t*)&hh;
}

// ============================================================================
// mask compaction (2 blocks, proven)
// ============================================================================
__global__ __launch_bounds__(1024)
void compact_kernel(const int* __restrict__ mask, int* __restrict__ idx,
                    int* __restrict__ nv)
{
    __shared__ int s[1024];
    const int b = blockIdx.x;
    const int t = threadIdx.x;
    const int m0 = mask[b * TT + 2 * t];
    const int m1 = mask[b * TT + 2 * t + 1];
    const int c  = m0 + m1;
    s[t] = c;
    __syncthreads();
    for (int off = 1; off < 1024; off <<= 1) {
        int v = s[t];
        int u = (t >= off) ? s[t - off] : 0;
        __syncthreads();
        s[t] = v + u;
        __syncthreads();
    }
    const int incl = s[t];
    const int excl = incl - c;
    if (m0) idx[b * TT + excl] = 2 * t;
    if (m1) idx[b * TT + excl + m0] = 2 * t + 1;
    if (t == 1023) nv[b] = incl;
}

// ============================================================================
// common GEMM geometry
// ============================================================================
#define GBK 32
#define NIT (KK / GBK)          // 32
#define BKP 40
#define ATILE (128 * BKP)
#define PROJ_SMEM (8 * ATILE * 2)   // 81920 B

// ============================================================================
// Fused Q/K/V projection + Wu-prep kernel (proven round-15/16 body).
// FLAT LPT-ordered grid (832 CTAs):
//   bid [0,256):   K-tiles   bid [256,512): Q-tiles
//   bid [512,768): V-tiles   bid [768,832): Wu fp32->fp16 filler
// ============================================================================
__global__ void __launch_bounds__(256)
proj_kernel(const float* __restrict__ x,
            const float* __restrict__ Wq,
            const float* __restrict__ Wk,
            const float* __restrict__ Wv,
            const float* __restrict__ Wu,
            const int* __restrict__ idx,
            const int* __restrict__ nvp,
            __nv_bfloat16* __restrict__ Qh, __nv_bfloat16* __restrict__ Ql,
            __nv_bfloat16* __restrict__ Kh, __nv_bfloat16* __restrict__ Kl,
            __half* __restrict__ Vf, __half* __restrict__ Wuf)
{
    extern __shared__ char smraw[];
    __shared__ int sidx[128];
    const uint32_t sbase = smem_u32(smraw);

    const int bid = blockIdx.x;

    if (bid >= 768) {
        const int base = (bid - 768) * 256 * 16 + threadIdx.x;
#pragma unroll
        for (int j = 0; j < 16; j++) {
            int i = base + j * 256;
            float4 f = ((const float4*)Wu)[i];
            uint2 o = { pack_h2(make_float2(f.x, f.y)), pack_h2(make_float2(f.z, f.w)) };
            ((uint2*)Wuf)[i] = o;
        }
        return;
    }

    int z, lbid;
    if (bid < 256)      { z = 1; lbid = bid; }
    else if (bid < 512) { z = 0; lbid = bid - 256; }
    else                { z = 2; lbid = bid - 512; }
    const int mt    = lbid >> 3;
    const int ntile = lbid & 7;

    const int tid  = threadIdx.x;
    const int lane = tid & 31;
    const int wid  = tid >> 5;
    const int g    = lane >> 2;
    const int tg   = lane & 3;
    const int wm   = wid & 1;
    const int wn   = wid >> 1;
    const int m0   = mt * 128;
    const int n0   = ntile * 128;

    if (z >= 1) {
        const int b = m0 / TT;
        const int s = m0 - b * TT;
        const int nvb = nvp[b];
        if (s >= nvb) return;
        if (tid < 128) {
            int ss = s + tid;
            sidx[tid] = b * TT + idx[b * TT + (ss < nvb ? ss : 0)];
        }
        __syncthreads();
    }

    const uint32_t aoff = (uint32_t)((wm * 64 + (lane & 15)) * BKP + ((lane & 16) ? 8 : 0));
    const uint32_t boff = (uint32_t)((wn * 32 + (lane & 7) + ((lane & 16) ? 8 : 0)) * BKP
                                     + ((lane & 8) ? 8 : 0));

    float4 ra[4], rb[4];

    if (z == 0) {
        const float* Agp = x  + (size_t)m0 * KK;
        const float* Bgp = Wq + (size_t)n0 * KK;

#define QLOAD(k0) do { \
    _Pragma("unroll") \
    for (int j = 0; j < 4; j++) { \
        int ix = j * 256 + tid; int row = ix >> 3; int c4 = ix & 7; \
        ra[j] = *(const float4*)(Agp + (size_t)row * KK + (k0) + c4 * 4); \
        rb[j] = *(const float4*)(Bgp + (size_t)row * KK + (k0) + c4 * 4); \
    } } while (0)

#define QSTORE(bsel) do { \
    _Pragma("unroll") \
    for (int j = 0; j < 4; j++) { \
        int ix = j * 256 + tid; int row = ix >> 3; int c4 = ix & 7; \
        uint32_t off = (uint32_t)((bsel) * 3 * ATILE + row * BKP + c4 * 4) * 2; \
        uint32_t h0, l0, h1, l1; \
        split2h(make_float2(ra[j].x, ra[j].y), h0, l0); \
        split2h(make_float2(ra[j].z, ra[j].w), h1, l1); \
        *(uint32_t*)(smraw + off)                 = h0; \
        *(uint32_t*)(smraw + off + 4)             = h1; \
        *(uint32_t*)(smraw + off + ATILE * 2)     = l0; \
        *(uint32_t*)(smraw + off + ATILE * 2 + 4) = l1; \
        *(uint32_t*)(smraw + off + 2 * ATILE * 2)     = pack_h2(make_float2(rb[j].x, rb[j].y)); \
        *(uint32_t*)(smraw + off + 2 * ATILE * 2 + 4) = pack_h2(make_float2(rb[j].z, rb[j].w)); \
    } } while (0)

        float acc [4][4][4];
        float acc2[4][4][4];
#pragma unroll
        for (int i = 0; i < 4; i++)
#pragma unroll
            for (int j = 0; j < 4; j++)
#pragma unroll
                for (int r = 0; r < 4; r++) { acc[i][j][r] = 0.f; acc2[i][j][r] = 0.f; }

        QLOAD(0);
        QSTORE(0);
        __syncthreads();

        for (int it = 0; it < NIT; it++) {
            const int buf = it & 1;
            if (it + 1 < NIT) QLOAD((it + 1) * GBK);

            const uint32_t bb = sbase + (uint32_t)(buf * 3 * ATILE) * 2;
#pragma unroll
            for (int ks = 0; ks < 2; ks++) {
                const uint32_t ko = ks * 32;
                uint32_t bf[4][2];
                LDSM4(bf[0][0], bf[0][1], bf[1][0], bf[1][1],
                      bb + 2 * ATILE * 2 + boff * 2 + ko);
                LDSM4(bf[2][0], bf[2][1], bf[3][0], bf[3][1],
                      bb + 2 * ATILE * 2 + (boff + 16 * BKP) * 2 + ko);
#pragma unroll
                for (int mf = 0; mf < 4; mf++) {
                    uint32_t ah0, ah1, ah2, ah3, al0, al1, al2, al3;
                    LDSM4(ah0, ah1, ah2, ah3, bb + (aoff + mf * 16 * BKP) * 2 + ko);
                    LDSM4(al0, al1, al2, al3, bb + ATILE * 2 + (aoff + mf * 16 * BKP) * 2 + ko);
#pragma unroll
                    for (int nf = 0; nf < 4; nf++) {
                        mma_f16f32(acc [mf][nf], ah0, ah1, ah2, ah3, bf[nf][0], bf[nf][1]);
                        mma_f16f32(acc2[mf][nf], al0, al1, al2, al3, bf[nf][0], bf[nf][1]);
                    }
                }
            }

            if (it + 1 < NIT) {
                __syncthreads();
                QSTORE(buf ^ 1);
                __syncthreads();
            }
        }
#undef QLOAD
#undef QSTORE

#pragma unroll
        for (int mf = 0; mf < 4; mf++) {
            int r0 = m0 + wm * 64 + mf * 16 + g;
#pragma unroll
            for (int nf = 0; nf < 4; nf++) {
                int col = n0 + wn * 32 + nf * 8 + tg * 2;
                float v00 = acc[mf][nf][0] + acc2[mf][nf][0] * INV2048;
                float v01 = acc[mf][nf][1] + acc2[mf][nf][1] * INV2048;
                float v10 = acc[mf][nf][2] + acc2[mf][nf][2] * INV2048;
                float v11 = acc[mf][nf][3] + acc2[mf][nf][3] * INV2048;
                uint32_t h0, l0, h1, l1;
                split2(make_float2(v00, v01), h0, l0);
                split2(make_float2(v10, v11), h1, l1);
                *(uint32_t*)&Qh[(size_t)r0 * KK + col]       = h0;
                *(uint32_t*)&Ql[(size_t)r0 * KK + col]       = l0;
                *(uint32_t*)&Qh[(size_t)(r0 + 8) * KK + col] = h1;
                *(uint32_t*)&Ql[(size_t)(r0 + 8) * KK + col] = l1;
            }
        }

    } else if (z == 1) {
        const float* Bgp = Wk + (size_t)n0 * KK;

#define KLOAD(k0) do { \
    _Pragma("unroll") \
    for (int j = 0; j < 4; j++) { \
        int ix = j * 256 + tid; int row = ix >> 3; int c4 = ix & 7; \
        ra[j] = *(const float4*)(x + (size_t)sidx[row] * KK + (k0) + c4 * 4); \
        rb[j] = *(const float4*)(Bgp + (size_t)row * KK + (k0) + c4 * 4); \
    } } while (0)

#define KSTORE(bsel) do { \
    _Pragma("unroll") \
    for (int j = 0; j < 4; j++) { \
        int ix = j * 256 + tid; int row = ix >> 3; int c4 = ix & 7; \
        uint32_t off = (uint32_t)((bsel) * 4 * ATILE + row * BKP + c4 * 4) * 2; \
        uint32_t h0, l0, h1, l1; \
        split2(make_float2(ra[j].x, ra[j].y), h0, l0); \
        split2(make_float2(ra[j].z, ra[j].w), h1, l1); \
        *(uint32_t*)(smraw + off)                 = h0; \
        *(uint32_t*)(smraw + off + 4)             = h1; \
        *(uint32_t*)(smraw + off + ATILE * 2)     = l0; \
        *(uint32_t*)(smraw + off + ATILE * 2 + 4) = l1; \
        split2(make_float2(rb[j].x, rb[j].y), h0, l0); \
        split2(make_float2(rb[j].z, rb[j].w), h1, l1); \
        *(uint32_t*)(smraw + off + 2 * ATILE * 2)     = h0; \
        *(uint32_t*)(smraw + off + 2 * ATILE * 2 + 4) = h1; \
        *(uint32_t*)(smraw + off + 3 * ATILE * 2)     = l0; \
        *(uint32_t*)(smraw + off + 3 * ATILE * 2 + 4) = l1; \
    } } while (0)

        float acc[4][4][4];
#pragma unroll
        for (int i = 0; i < 4; i++)
#pragma unroll
            for (int j = 0; j < 4; j++)
#pragma unroll
                for (int r = 0; r < 4; r++) acc[i][j][r] = 0.f;

        KLOAD(0);
        KSTORE(0);
        __syncthreads();

        for (int it = 0; it < NIT; it++) {
            const int buf = it & 1;
            if (it + 1 < NIT) KLOAD((it + 1) * GBK);

            const uint32_t bb = sbase + (uint32_t)(buf * 4 * ATILE) * 2;
#pragma unroll
            for (int ks = 0; ks < 2; ks++) {
                const uint32_t ko = ks * 32;
                uint32_t bh[4][2], bl[4][2];
                LDSM4(bh[0][0], bh[0][1], bh[1][0], bh[1][1],
                      bb + 2 * ATILE * 2 + boff * 2 + ko);
                LDSM4(bh[2][0], bh[2][1], bh[3][0], bh[3][1],
                      bb + 2 * ATILE * 2 + (boff + 16 * BKP) * 2 + ko);
                LDSM4(bl[0][0], bl[0][1], bl[1][0], bl[1][1],
                      bb + 3 * ATILE * 2 + boff * 2 + ko);
                LDSM4(bl[2][0], bl[2][1], bl[3][0], bl[3][1],
                      bb + 3 * ATILE * 2 + (boff + 16 * BKP) * 2 + ko);
#pragma unroll
                for (int mf = 0; mf < 4; mf++) {
                    uint32_t ah0, ah1, ah2, ah3, al0, al1, al2, al3;
                    LDSM4(ah0, ah1, ah2, ah3, bb + (aoff + mf * 16 * BKP) * 2 + ko);
                    LDSM4(al0, al1, al2, al3, bb + ATILE * 2 + (aoff + mf * 16 * BKP) * 2 + ko);
#pragma unroll
                    for (int nf = 0; nf < 4; nf++) {
                        mma_bf16(acc[mf][nf], ah0, ah1, ah2, ah3, bh[nf][0], bh[nf][1]);
                        mma_bf16(acc[mf][nf], ah0, ah1, ah2, ah3, bl[nf][0], bl[nf][1]);
                        mma_bf16(acc[mf][nf], al0, al1, al2, al3, bh[nf][0], bh[nf][1]);
                    }
                }
            }

            if (it + 1 < NIT) {
                __syncthreads();
                KSTORE(buf ^ 1);
                __syncthreads();
            }
        }
#undef KLOAD
#undef KSTORE

#pragma unroll
        for (int mf = 0; mf < 4; mf++) {
            int r0 = m0 + wm * 64 + mf * 16 + g;
#pragma unroll
            for (int nf = 0; nf < 4; nf++) {
                int col = n0 + wn * 32 + nf * 8 + tg * 2;
                uint32_t h0, l0, h1, l1;
                split2(make_float2(acc[mf][nf][0], acc[mf][nf][1]), h0, l0);
                split2(make_float2(acc[mf][nf][2], acc[mf][nf][3]), h1, l1);
                *(uint32_t*)&Kh[(size_t)r0 * KK + col]       = h0;
                *(uint32_t*)&Kl[(size_t)r0 * KK + col]       = l0;
                *(uint32_t*)&Kh[(size_t)(r0 + 8) * KK + col] = h1;
                *(uint32_t*)&Kl[(size_t)(r0 + 8) * KK + col] = l1;
            }
        }

    } else {
        const float* Bgp = Wv + (size_t)n0 * KK;

#define VLOAD(k0) do { \
    _Pragma("unroll") \
    for (int j = 0; j < 4; j++) { \
        int ix = j * 256 + tid; int row = ix >> 3; int c4 = ix & 7; \
        ra[j] = *(const float4*)(x + (size_t)sidx[row] * KK + (k0) + c4 * 4); \
        rb[j] = *(const float4*)(Bgp + (size_t)row * KK + (k0) + c4 * 4); \
    } } while (0)

#define VSTORE(bsel) do { \
    _Pragma("unroll") \
    for (int j = 0; j < 4; j++) { \
        int ix = j * 256 + tid; int row = ix >> 3; int c4 = ix & 7; \
        uint32_t off = (uint32_t)((bsel) * 2 * ATILE + row * BKP + c4 * 4) * 2; \
        *(uint32_t*)(smraw + off)     = pack_h2(make_float2(ra[j].x, ra[j].y)); \
        *(uint32_t*)(smraw + off + 4) = pack_h2(make_float2(ra[j].z, ra[j].w)); \
        *(uint32_t*)(smraw + off + ATILE * 2)     = pack_h2(make_float2(rb[j].x, rb[j].y)); \
        *(uint32_t*)(smraw + off + ATILE * 2 + 4) = pack_h2(make_float2(rb[j].z, rb[j].w)); \
    } } while (0)

        float acc[4][4][4];
#pragma unroll
        for (int i = 0; i < 4; i++)
#pragma unroll
            for (int j = 0; j < 4; j++)
#pragma unroll
                for (int r = 0; r < 4; r++) acc[i][j][r] = 0.f;

        VLOAD(0);
        VSTORE(0);
        __syncthreads();

        for (int it = 0; it < NIT; it++) {
            const int buf = it & 1;
            if (it + 1 < NIT) VLOAD((it + 1) * GBK);

            const uint32_t bb = sbase + (uint32_t)(buf * 2 * ATILE) * 2;
#pragma unroll
            for (int ks = 0; ks < 2; ks++) {
                const uint32_t ko = ks * 32;
                uint32_t bf[4][2];
                LDSM4(bf[0][0], bf[0][1], bf[1][0], bf[1][1],
                      bb + ATILE * 2 + boff * 2 + ko);
                LDSM4(bf[2][0], bf[2][1], bf[3][0], bf[3][1],
                      bb + ATILE * 2 + (boff + 16 * BKP) * 2 + ko);
#pragma unroll
                for (int mf = 0; mf < 4; mf++) {
                    uint32_t a0, a1, a2, a3;
                    LDSM4(a0, a1, a2, a3, bb + (aoff + mf * 16 * BKP) * 2 + ko);
#pragma unroll
                    for (int nf = 0; nf < 4; nf++)
                        mma_f16f32(acc[mf][nf], a0, a1, a2, a3, bf[nf][0], bf[nf][1]);
                }
            }

            if (it + 1 < NIT) {
                __syncthreads();
                VSTORE(buf ^ 1);
                __syncthreads();
            }
        }
#undef VLOAD
#undef VSTORE

#pragma unroll
        for (int mf = 0; mf < 4; mf++) {
            int r0 = m0 + wm * 64 + mf * 16 + g;
#pragma unroll
            for (int nf = 0; nf < 4; nf++) {
                int col = n0 + wn * 32 + nf * 8 + tg * 2;
                *(uint32_t*)&Vf[(size_t)r0 * KK + col] =
                    pack_h2(make_float2(acc[mf][nf][0], acc[mf][nf][1]));
                *(uint32_t*)&Vf[(size_t)(r0 + 8) * KK + col] =
                    pack_h2(make_float2(acc[mf][nf][2], acc[mf][nf][3]));
            }
        }
    }
}

// ============================================================================
// gemm1: 1-term fp16, 3-stage cp.async ring (wait_group 1). 2 CTAs/SM.
// ============================================================================
#define G1STG 3
#define G1SMEM (G1STG * 2 * ATILE * 2)   // 61440 B

__global__ void __launch_bounds__(256, 2)
gemm1_kernel(const __half* __restrict__ Ag,
             const __half* __restrict__ Bg,
             const float* __restrict__ bias,
             float* __restrict__ Cf,
             int M, int N)
{
    extern __shared__ __half sm1[];
    const uint32_t sbase = smem_u32(sm1);

    const int tid  = threadIdx.x;
    const int lane = tid & 31;
    const int wid  = tid >> 5;
    const int g    = lane >> 2;
    const int tg   = lane & 3;
    const int wm   = wid & 1;
    const int wn   = wid >> 1;
    const int m0   = blockIdx.y * 128;
    const int n0   = blockIdx.x * 128;

    const __half* gsrc[2] = { Ag + (size_t)m0 * KK, Bg + (size_t)n0 * KK };

    const uint32_t aoff = (uint32_t)((wm * 64 + (lane & 15)) * BKP + ((lane & 16) ? 8 : 0));
    const uint32_t boff = (uint32_t)((wn * 32 + (lane & 7) + ((lane & 16) ? 8 : 0)) * BKP
                                     + ((lane & 8) ? 8 : 0));

#define G1ISSUE(k0, st) do { \
    _Pragma("unroll") \
    for (int a = 0; a < 2; a++) { \
        uint32_t sd = sbase + (uint32_t)(((st) * 2 + a) * ATILE) * 2; \
        _Pragma("unroll") \
        for (int j = 0; j < 2; j++) { \
            int row = j * 64 + (tid >> 2); int cc = tid & 3; \
            uint32_t s = sd + (uint32_t)(row * BKP + cc * 8) * 2; \
            const __half* gp = gsrc[a] + (size_t)row * KK + (k0) + cc * 8; \
            asm volatile("cp.async.cg.shared.global [%0], [%1], 16;" :: "r"(s), "l"(gp)); \
        } \
    } \
    asm volatile("cp.async.commit_group;"); \
} while (0)

    float acc[4][4][4];
#pragma unroll
    for (int i = 0; i < 4; i++)
#pragma unroll
        for (int j = 0; j < 4; j++)
#pragma unroll
            for (int r = 0; r < 4; r++) acc[i][j][r] = 0.f;

    G1ISSUE(0, 0);
    G1ISSUE(GBK, 1);

    int st = 0;
    for (int it = 0; it < NIT; it++) {
        if (it + 1 < NIT) asm volatile("cp.async.wait_group 1;");
        else              asm volatile("cp.async.wait_group 0;");
        __syncthreads();
        if (it + 2 < NIT) {
            int ns = st + 2; if (ns >= G1STG) ns -= G1STG;
            G1ISSUE((it + 2) * GBK, ns);
        }

        const uint32_t bb = sbase + (uint32_t)(st * 2 * ATILE) * 2;
#pragma unroll
        for (int ks = 0; ks < 2; ks++) {
            const uint32_t ko = ks * 32;
            uint32_t bf[4][2];
            LDSM4(bf[0][0], bf[0][1], bf[1][0], bf[1][1],
                  bb + ATILE * 2 + boff * 2 + ko);
            LDSM4(bf[2][0], bf[2][1], bf[3][0], bf[3][1],
                  bb + ATILE * 2 + (boff + 16 * BKP) * 2 + ko);
#pragma unroll
            for (int mf = 0; mf < 4; mf++) {
                uint32_t a0, a1, a2, a3;
                LDSM4(a0, a1, a2, a3, bb + (aoff + mf * 16 * BKP) * 2 + ko);
#pragma unroll
                for (int nf = 0; nf < 4; nf++)
                    mma_f16f32(acc[mf][nf], a0, a1, a2, a3, bf[nf][0], bf[nf][1]);
            }
        }

        if (++st >= G1STG) st = 0;
    }
#undef G1ISSUE

#pragma unroll
    for (int mf = 0; mf < 4; mf++) {
        int r0 = m0 + wm * 64 + mf * 16 + g;
#pragma unroll
        for (int nf = 0; nf < 4; nf++) {
            int col = n0 + wn * 32 + nf * 8 + tg * 2;
            float b0 = __ldg(&bias[col]), b1 = __ldg(&bias[col + 1]);
            float2 o0 = { acc[mf][nf][0] + b0, acc[mf][nf][1] + b1 };
            float2 o1 = { acc[mf][nf][2] + b0, acc[mf][nf][3] + b1 };
            *(float2*)&Cf[(size_t)r0 * N + col]       = o0;
            *(float2*)&Cf[(size_t)(r0 + 8) * N + col] = o1;
        }
    }
}

// ============================================================================
// Flash attention (proven round-13 body).
// ============================================================================
#define AST 72
#define KVTILE (64 * AST * 2)
#define ASTAGE (3 * KVTILE)
#define ATTN_SMEM (2 * ASTAGE)

__global__ __launch_bounds__(128, 2)
void attn_tc_kernel(const __nv_bfloat16* __restrict__ Qh_,
                    const __nv_bfloat16* __restrict__ Ql_,
                    const __nv_bfloat16* __restrict__ Kh_,
                    const __nv_bfloat16* __restrict__ Kl_,
                    const __half* __restrict__ Vf_,
                    const int* __restrict__ nvp,
                    __half* __restrict__ ysf)
{
    extern __shared__ char asmem[];
    const uint32_t sbase = smem_u32(asmem);

    const int tid  = threadIdx.x;
    const int lane = tid & 31;
    const int w    = tid >> 5;
    const int g    = lane >> 2;
    const int tg   = lane & 3;
    const int b    = blockIdx.z;
    const int h    = blockIdx.y;
    const int q0   = blockIdx.x * 128;

    const int nvb    = nvp[b];
    const int ntiles = (nvb + 63) >> 6;

    const __nv_bfloat16* Qhb = Qh_ + (size_t)(b * TT + q0 + w * 32) * KK + h * SS;
    const __nv_bfloat16* Qlb = Ql_ + (size_t)(b * TT + q0 + w * 32) * KK + h * SS;
    uint32_t qh_[2][4][4], ql_[2][4][4];
#pragma unroll
    for (int m = 0; m < 2; m++) {
#pragma unroll
        for (int ks = 0; ks < 4; ks++) {
            int r0 = m * 16 + g, r1 = r0 + 8;
            int d0 = ks * 16 + 2 * tg;
            qh_[m][ks][0] = *(const uint32_t*)(Qhb + (size_t)r0 * KK + d0);
            qh_[m][ks][1] = *(const uint32_t*)(Qhb + (size_t)r1 * KK + d0);
            qh_[m][ks][2] = *(const uint32_t*)(Qhb + (size_t)r0 * KK + d0 + 8);
            qh_[m][ks][3] = *(const uint32_t*)(Qhb + (size_t)r1 * KK + d0 + 8);
            ql_[m][ks][0] = *(const uint32_t*)(Qlb + (size_t)r0 * KK + d0);
            ql_[m][ks][1] = *(const uint32_t*)(Qlb + (size_t)r1 * KK + d0);
            ql_[m][ks][2] = *(const uint32_t*)(Qlb + (size_t)r0 * KK + d0 + 8);
            ql_[m][ks][3] = *(const uint32_t*)(Qlb + (size_t)r1 * KK + d0 + 8);
        }
    }

    float o[2][8][4];
#pragma unroll
    for (int m = 0; m < 2; m++)
#pragma unroll
        for (int nt = 0; nt < 8; nt++)
#pragma unroll
            for (int c = 0; c < 4; c++) o[m][nt][c] = 0.f;
    float mr[2][2] = { {-1e30f, -1e30f}, {-1e30f, -1e30f} };
    float lr[2][2] = { {0.f, 0.f}, {0.f, 0.f} };

    const __nv_bfloat16* Khb = Kh_ + (size_t)b * TT * KK + h * SS;
    const __nv_bfloat16* Klb = Kl_ + (size_t)b * TT * KK + h * SS;
    const __half*        Vfb = Vf_ + (size_t)b * TT * KK + h * SS;

    const uint32_t vlb = (uint32_t)((lane & 15) * AST + ((lane & 16) ? 8 : 0)) * 2;

#define AISSUE(kt, st) do { \
    uint32_t sd = sbase + (uint32_t)(st) * ASTAGE; \
    _Pragma("unroll") \
    for (int i = 0; i < 4; i++) { \
        int ix = i * 128 + tid; int row = ix >> 3; int ch = ix & 7; \
        uint32_t dd = sd + (uint32_t)(row * AST * 2 + ch * 16); \
        const __nv_bfloat16* s0 = Khb + (size_t)((kt) * 64 + row) * KK + ch * 8; \
        const __nv_bfloat16* s1 = Klb + (size_t)((kt) * 64 + row) * KK + ch * 8; \
        const __half*        s2 = Vfb + (size_t)((kt) * 64 + row) * KK + ch * 8; \
        asm volatile("cp.async.cg.shared.global [%0], [%1], 16;" :: "r"(dd), "l"(s0)); \
        asm volatile("cp.async.cg.shared.global [%0], [%1], 16;" :: "r"(dd + KVTILE), "l"(s1)); \
        asm volatile("cp.async.cg.shared.global [%0], [%1], 16;" :: "r"(dd + 2 * KVTILE), "l"(s2)); \
    } \
    asm volatile("cp.async.commit_group;"); \
} while (0)

    AISSUE(0, 0);

    for (int kt = 0; kt < ntiles; kt++) {
        const int st = kt & 1;
        __syncthreads();
        if (kt + 1 < ntiles) {
            AISSUE(kt + 1, st ^ 1);
            asm volatile("cp.async.wait_group 1;");
        } else {
            asm volatile("cp.async.wait_group 0;");
        }
        __syncthreads();

        const char* stage = asmem + st * ASTAGE;
        const __nv_bfloat16* kh = (const __nv_bfloat16*)stage;
        const __nv_bfloat16* kl = (const __nv_bfloat16*)(stage + KVTILE);
        const uint32_t vbase = sbase + (uint32_t)st * ASTAGE + 2 * KVTILE;

        float s[2][8][4];
#pragma unroll
        for (int m = 0; m < 2; m++)
#pragma unroll
            for (int nt = 0; nt < 8; nt++)
#pragma unroll
                for (int c = 0; c < 4; c++) s[m][nt][c] = 0.f;

#pragma unroll
        for (int ks = 0; ks < 4; ks++) {
            const int kk = ks * 16 + 2 * tg;
#pragma unroll
            for (int nt = 0; nt < 8; nt++) {
                const int rr = (nt * 8 + g) * AST + kk;
                uint32_t bh0 = *(const uint32_t*)&kh[rr];
                uint32_t bh1 = *(const uint32_t*)&kh[rr + 8];
                uint32_t bl0 = *(const uint32_t*)&kl[rr];
                uint32_t bl1 = *(const uint32_t*)&kl[rr + 8];
#pragma unroll
                for (int m = 0; m < 2; m++) {
                    mma_bf16(s[m][nt], qh_[m][ks][0], qh_[m][ks][1], qh_[m][ks][2], qh_[m][ks][3], bh0, bh1);
                    mma_bf16(s[m][nt], qh_[m][ks][0], qh_[m][ks][1], qh_[m][ks][2], qh_[m][ks][3], bl0, bl1);
                    mma_bf16(s[m][nt], ql_[m][ks][0], ql_[m][ks][1], ql_[m][ks][2], ql_[m][ks][3], bh0, bh1);
                }
            }
        }

        if (kt * 64 + 64 > nvb) {
#pragma unroll
            for (int nt = 0; nt < 8; nt++) {
                int c0 = kt * 64 + nt * 8 + 2 * tg;
                if (c0 >= nvb) {
                    s[0][nt][0] = s[0][nt][2] = -1e30f;
                    s[1][nt][0] = s[1][nt][2] = -1e30f;
                }
                if (c0 + 1 >= nvb) {
                    s[0][nt][1] = s[0][nt][3] = -1e30f;
                    s[1][nt][1] = s[1][nt][3] = -1e30f;
                }
            }
        }

#pragma unroll
        for (int m = 0; m < 2; m++) {
#pragma unroll
            for (int r2 = 0; r2 < 2; r2++) {
                const int c0 = r2 * 2;
                float tmax = -1e30f;
#pragma unroll
                for (int nt = 0; nt < 8; nt++) {
                    tmax = fmaxf(tmax, s[m][nt][c0]);
                    tmax = fmaxf(tmax, s[m][nt][c0 + 1]);
                }
                tmax = fmaxf(tmax, __shfl_xor_sync(0xffffffffu, tmax, 1));
                tmax = fmaxf(tmax, __shfl_xor_sync(0xffffffffu, tmax, 2));
                float mn = fmaxf(mr[m][r2], tmax);
                float sc = __expf(mr[m][r2] - mn);
                mr[m][r2] = mn;
                float ts = 0.f;
#pragma unroll
                for (int nt = 0; nt < 8; nt++) {
                    float p0 = __expf(s[m][nt][c0]     - mn);
                    float p1 = __expf(s[m][nt][c0 + 1] - mn);
                    s[m][nt][c0]     = p0;
                    s[m][nt][c0 + 1] = p1;
                    ts += p0 + p1;
                }
                ts += __shfl_xor_sync(0xffffffffu, ts, 1);
                ts += __shfl_xor_sync(0xffffffffu, ts, 2);
                lr[m][r2] = lr[m][r2] * sc + ts;
#pragma unroll
                for (int nt = 0; nt < 8; nt++) {
                    o[m][nt][c0]     *= sc;
                    o[m][nt][c0 + 1] *= sc;
                }
            }
        }

#pragma unroll
        for (int ks = 0; ks < 4; ks++) {
            uint32_t ph[2][4];
#pragma unroll
            for (int m = 0; m < 2; m++) {
                ph[m][0] = pack_h2(make_float2(s[m][2*ks][0],   s[m][2*ks][1]));
                ph[m][1] = pack_h2(make_float2(s[m][2*ks][2],   s[m][2*ks][3]));
                ph[m][2] = pack_h2(make_float2(s[m][2*ks+1][0], s[m][2*ks+1][1]));
                ph[m][3] = pack_h2(make_float2(s[m][2*ks+1][2], s[m][2*ks+1][3]));
            }
            const uint32_t krow = (uint32_t)(ks * 16 * AST * 2);
#pragma unroll
            for (int dp = 0; dp < 4; dp++) {
                uint32_t v0, v1, v2, v3;
                LDSM4T(v0, v1, v2, v3, vbase + krow + (uint32_t)(dp * 32) + vlb);
#pragma unroll
                for (int m = 0; m < 2; m++) {
                    mma_f16f32(o[m][2*dp],     ph[m][0], ph[m][1], ph[m][2], ph[m][3], v0, v1);
                    mma_f16f32(o[m][2*dp + 1], ph[m][0], ph[m][1], ph[m][2], ph[m][3], v2, v3);
                }
            }
        }
    }
#undef AISSUE

#pragma unroll
    for (int m = 0; m < 2; m++) {
#pragma unroll
        for (int r2 = 0; r2 < 2; r2++) {
            float inv = 1.f / lr[m][r2];
            int row = q0 + w * 32 + m * 16 + g + r2 * 8;
            size_t off = (size_t)(b * TT + row) * KK + h * SS;
#pragma unroll
            for (int nt = 0; nt < 8; nt++) {
                *(uint32_t*)&ysf[off + nt * 8 + 2 * tg] =
                    pack_h2(make_float2(o[m][nt][r2*2] * inv, o[m][nt][r2*2+1] * inv));
            }
        }
    }
}

// ============================================================================
// launch
// ============================================================================
extern "C" void kernel_launch(void* const* d_in, const int* in_sizes, int n_in,
                              void* d_out, int out_size)
{
    const float* x    = (const float*)d_in[0];
    const int*   mask = (const int*)  d_in[1];
    const float* Wk   = (const float*)d_in[2];
    const float* Wq   = (const float*)d_in[3];
    const float* Wv   = (const float*)d_in[4];
    const float* Wu   = (const float*)d_in[5];
    const float* bu   = (const float*)d_in[6];
    float* out = (float*)d_out;

    __nv_bfloat16 *Qh, *Ql, *Kh, *Kl;
    __half *Wuf, *Vf, *ysf;
    int *idx, *nv;
    cudaGetSymbolAddress((void**)&Qh,  g_Qh);  cudaGetSymbolAddress((void**)&Ql,  g_Ql);
    cudaGetSymbolAddress((void**)&Kh,  g_Kh);  cudaGetSymbolAddress((void**)&Kl,  g_Kl);
    cudaGetSymbolAddress((void**)&Wuf, g_Wuf);
    cudaGetSymbolAddress((void**)&Vf,  g_Vf);  cudaGetSymbolAddress((void**)&ysf, g_ysf);
    cudaGetSymbolAddress((void**)&idx, g_idx); cudaGetSymbolAddress((void**)&nv,  g_nv);

    cudaFuncSetAttribute(proj_kernel,
                         cudaFuncAttributeMaxDynamicSharedMemorySize, PROJ_SMEM);
    cudaFuncSetAttribute(gemm1_kernel,
                         cudaFuncAttributeMaxDynamicSharedMemorySize, G1SMEM);
    cudaFuncSetAttribute(attn_tc_kernel,
                         cudaFuncAttributeMaxDynamicSharedMemorySize, ATTN_SMEM);

    compact_kernel<<<BB, 1024>>>(mask, idx, nv);

    // LPT flat grid: 256 K + 256 Q + 256 V tiles, then 64 Wu-prep fillers
    proj_kernel<<<832, 256, PROJ_SMEM>>>(x, Wq, Wk, Wv, Wu, idx, nv,
                                         Qh, Ql, Kh, Kl, Vf, Wuf);

    dim3 ga(TT / 128, HH, BB);           // (16, 16, 2)
    attn_tc_kernel<<<ga, 128, ATTN_SMEM>>>(Qh, Ql, Kh, Kl, Vf, nv, ysf);

    dim3 gu(KK / 128, MROWS / 128);      // (8, 32)
    gemm1_kernel<<<gu, 256, G1SMEM>>>(ysf, Wuf, bu, out, MROWS, KK);
}